// round 2
// baseline (speedup 1.0000x reference)
#include <cuda_runtime.h>

#define BB 128
#define PP 4096
#define NN 64

typedef unsigned long long ull;

// Packed per-center-PAIR coefficients: element j holds {val(2j), val(2j+1)}
// q[n](x) = K + a0*x0^2 + b0*x0 + a1*x1^2 + b1*x1,  exp(-dist) = EX2(q)
__device__ ull gA0[NN / 2];
__device__ ull gB0[NN / 2];
__device__ ull gA1[NN / 2];
__device__ ull gB1[NN / 2];
__device__ ull gK [NN / 2];

__device__ __forceinline__ ull pack2(float lo, float hi) {
    ull d;
    asm("mov.b64 %0, {%1, %2};" : "=l"(d) : "f"(lo), "f"(hi));
    return d;
}
__device__ __forceinline__ void unpack2(ull v, float& lo, float& hi) {
    asm("mov.b64 {%0, %1}, %2;" : "=f"(lo), "=f"(hi) : "l"(v));
}
__device__ __forceinline__ ull fma2(ull a, ull b, ull c) {
    ull d;
    asm("fma.rn.f32x2 %0, %1, %2, %3;" : "=l"(d) : "l"(a), "l"(b), "l"(c));
    return d;
}
__device__ __forceinline__ ull mul2(ull a, ull b) {
    ull d;
    asm("mul.rn.f32x2 %0, %1, %2;" : "=l"(d) : "l"(a), "l"(b));
    return d;
}
__device__ __forceinline__ float ex2f(float q) {
    float e;
    asm("ex2.approx.ftz.f32 %0, %1;" : "=f"(e) : "f"(q));
    return e;
}

__global__ void slayer_precompute(const float* __restrict__ centers,
                                  const float* __restrict__ sharp) {
    int j = threadIdx.x;          // pair index: centers (2j, 2j+1)
    if (j < NN / 2) {
        const float L = 1.4426950408889634f;  // log2(e)
        float a0v[2], b0v[2], a1v[2], b1v[2], kv[2];
#pragma unroll
        for (int k = 0; k < 2; k++) {
            int n = 2 * j + k;
            float c0 = centers[2 * n], c1 = centers[2 * n + 1];
            float s0 = sharp[2 * n],   s1 = sharp[2 * n + 1];
            float a0 = -L * s0 * s0;
            float a1 = -L * s1 * s1;
            a0v[k] = a0;
            a1v[k] = a1;
            b0v[k] = -2.0f * a0 * c0;
            b1v[k] = -2.0f * a1 * c1;
            kv[k]  = a0 * c0 * c0 + a1 * c1 * c1;
        }
        gA0[j] = pack2(a0v[0], a0v[1]);
        gB0[j] = pack2(b0v[0], b0v[1]);
        gA1[j] = pack2(a1v[0], a1v[1]);
        gB1[j] = pack2(b1v[0], b1v[1]);
        gK [j] = pack2(kv[0],  kv[1]);
    }
}

// One block per batch. 1024 threads = 32 warps.
//   warp & 15 -> center group (16 groups x 4 centers = 2 packed pairs)
//   warp >> 4 -> point half (2 x 2048 points)
// Per point, per center-pair: 4 packed FFMA + unpack + 2 EX2 + pack + packed acc FFMA.
__global__ __launch_bounds__(1024, 1) void slayer_main(
    const float2* __restrict__ batch,   // [B, P] float2
    const float*  __restrict__ mask,    // [B, P]
    float*        __restrict__ out)     // [B, N]
{
    const int b    = blockIdx.x;
    const int tid  = threadIdx.x;
    const int warp = tid >> 5;
    const int lane = tid & 31;
    const int g    = warp & 15;   // center group: centers 4g..4g+3, pairs 2g,2g+1
    const int half = warp >> 4;

    // Register-resident packed coefficients for 2 center-pairs
    ull A0[2], B0[2], A1[2], B1[2], KK[2], acc[2];
#pragma unroll
    for (int j = 0; j < 2; j++) {
        A0[j] = gA0[2 * g + j];
        B0[j] = gB0[2 * g + j];
        A1[j] = gA1[2 * g + j];
        B1[j] = gB1[2 * g + j];
        KK[j] = gK [2 * g + j];
        acc[j] = 0ULL;            // {0.0f, 0.0f}
    }

    const float2* bp = batch + (size_t)b * PP + half * (PP / 2);
    const float*  mp = mask  + (size_t)b * PP + half * (PP / 2);

    constexpr int ITERS = (PP / 2) / 32;   // 64

#pragma unroll 4
    for (int it = 0; it < ITERS; it++) {
        const int p = it * 32 + lane;
        const float2 x = __ldg(bp + p);
        const float  m = __ldg(mp + p);

        const ull X0  = pack2(x.x, x.x);
        const ull X1  = pack2(x.y, x.y);
        const ull MM  = pack2(m, m);
        const ull X00 = mul2(X0, X0);
        const ull X11 = mul2(X1, X1);

#pragma unroll
        for (int j = 0; j < 2; j++) {
            ull q = KK[j];
            q = fma2(A0[j], X00, q);
            q = fma2(B0[j], X0,  q);
            q = fma2(A1[j], X11, q);
            q = fma2(B1[j], X1,  q);
            float qlo, qhi;
            unpack2(q, qlo, qhi);
            const ull e = pack2(ex2f(qlo), ex2f(qhi));
            acc[j] = fma2(MM, e, acc[j]);
        }
    }

    // Unpack the 4 per-center accumulators and reduce over the 32 point-lanes
    float s[4];
    unpack2(acc[0], s[0], s[1]);
    unpack2(acc[1], s[2], s[3]);
#pragma unroll
    for (int off = 16; off > 0; off >>= 1) {
#pragma unroll
        for (int j = 0; j < 4; j++)
            s[j] += __shfl_xor_sync(0xffffffffu, s[j], off);
    }

    // Combine the two point-halves deterministically via shared memory
    __shared__ float partial[2][NN];
    if (lane == 0) {
#pragma unroll
        for (int j = 0; j < 4; j++)
            partial[half][4 * g + j] = s[j];
    }
    __syncthreads();

    if (tid < NN)
        out[b * NN + tid] = partial[0][tid] + partial[1][tid];
}

extern "C" void kernel_launch(void* const* d_in, const int* in_sizes, int n_in,
                              void* d_out, int out_size) {
    const float* batch   = (const float*)d_in[0];   // [B,P,D] f32
    const float* mask    = (const float*)d_in[1];   // [B,P]   f32
    const float* centers = (const float*)d_in[2];   // [N,D]   f32
    const float* sharp   = (const float*)d_in[3];   // [N,D]   f32
    float* out = (float*)d_out;                     // [B,N]   f32

    slayer_precompute<<<1, 32>>>(centers, sharp);
    slayer_main<<<BB, 1024>>>((const float2*)batch, mask, out);
}